// round 7
// baseline (speedup 1.0000x reference)
#include <cuda_runtime.h>
#include <cstdint>

// ============================================================================
// out[8192,4096] = sign(x) @ sign(w).
// Round-6: DUAL-PIPE CONCURRENCY.
//   rows 0..5375   : XOR+CSA popcount GEMM  (ALU pipe, ~990us solo full-M)
//   rows 5376..8191: legacy s8 mma.sync GEMM (tensor pipe, ~1900us solo full-M)
// Both launched on forked capture streams -> parallel graph branches ->
// co-resident blocks keep ALU and tensor pipes busy simultaneously.
// All arithmetic exact (+/-1 products, s32 accumulation).
// ============================================================================

static constexpr int MDIM = 8192;
static constexpr int NDIM = 4096;
static constexpr int KDIM = 4096;
static constexpr int KW   = KDIM / 32;   // 128 words

// ---- popc path (rows 0..5375) ----
static constexpr int MT_P = 84;          // 64-row tiles
static constexpr int NT_P = 64;          // 64-col tiles
static constexpr int CHUNK_W = 32;
static constexpr int NCHUNK  = KW / CHUNK_W;       // 4
static constexpr int CHUNK_WORDS = CHUNK_W * 64;   // 2048

// ---- s8 mma path (rows 5376..8191) ----
static constexpr int MT_S = 22;          // 128-row tiles
static constexpr int NT_S = 16;          // 256-col tiles
static constexpr int KT_S = 64;          // 64-byte K tiles
static constexpr int A_TILE8 = 128 * 64;            // 8192 B
static constexpr int B_TILE8 = 256 * 64;            // 16384 B
static constexpr int STAGE8  = A_TILE8 + B_TILE8;
static constexpr int SMEM8   = 4 * STAGE8;          // 98304

// Scratch
__device__ __align__(16) uint32_t g_xbits[(size_t)MT_P * KW * 64];            // 2.75 MB
__device__ __align__(16) uint32_t g_wbits[(size_t)NT_P * KW * 64];            // 2 MB
__device__ __align__(16) unsigned char g_xa8[(size_t)MT_S * KT_S * A_TILE8];  // 11.5 MB
__device__ __align__(16) unsigned char g_wb8[(size_t)NT_S * KT_S * B_TILE8];  // 16 MB

// ---------------------------------------------------------------------------
// shared helpers
// ---------------------------------------------------------------------------
__device__ __forceinline__ uint32_t smem_u32(const void* p) {
    uint32_t a;
    asm("{ .reg .u64 t; cvta.to.shared.u64 t, %1; cvt.u32.u64 %0, t; }" : "=r"(a) : "l"(p));
    return a;
}
__device__ __forceinline__ uint32_t lds32(uint32_t addr) {
    uint32_t v;
    asm volatile("ld.shared.u32 %0, [%1];" : "=r"(v) : "r"(addr));
    return v;
}
__device__ __forceinline__ void cpasync16(uint32_t s, const void* g) {
    asm volatile("cp.async.cg.shared.global [%0], [%1], 16;" :: "r"(s), "l"(g));
}
#define CP_COMMIT() asm volatile("cp.async.commit_group;" ::: "memory")
#define CP_WAITN(n) asm volatile("cp.async.wait_group %0;" :: "n"(n) : "memory")

__device__ __forceinline__ void mma_s8(int* c, const uint32_t* a, const uint32_t* b) {
    asm volatile(
        "mma.sync.aligned.m16n8k32.row.col.s32.s8.s8.s32 "
        "{%0,%1,%2,%3}, {%4,%5,%6,%7}, {%8,%9}, {%0,%1,%2,%3};"
        : "+r"(c[0]), "+r"(c[1]), "+r"(c[2]), "+r"(c[3])
        : "r"(a[0]), "r"(a[1]), "r"(a[2]), "r"(a[3]), "r"(b[0]), "r"(b[1]));
}
__device__ __forceinline__ uint32_t swoff8(int r, int w) {
    int sw = (w >> 2) ^ ((r ^ (r >> 2)) & 3);
    return (uint32_t)(r * 64 + (sw << 4) + ((w & 3) << 2));
}
__device__ __forceinline__ unsigned char sgn_s8(float v) { return (v >= 0.0f) ? 0x01 : 0xFF; }

// ===========================================================================
// POPC PATH (rows 0..5375)
// ===========================================================================
__global__ void __launch_bounds__(256) k_packx(const float* __restrict__ x) {
    int m    = blockIdx.x * 8 + (threadIdx.x >> 5);       // 0..5375
    int lane = threadIdx.x & 31;
    const float* row = x + (size_t)m * KDIM;
    uint32_t mt = (uint32_t)m >> 6, ml = (uint32_t)m & 63u;
    #pragma unroll 4
    for (int w = 0; w < KW; w++) {
        float v = row[w * 32 + lane];
        uint32_t bits = __ballot_sync(0xffffffffu, v < 0.0f);
        if (lane == 0)
            g_xbits[((size_t)(mt * 4u + ((uint32_t)w >> 5)) * 32u + ((uint32_t)w & 31u)) * 64u + ml] = bits;
    }
}

__global__ void __launch_bounds__(256) k_packw(const float* __restrict__ w) {
    uint32_t q  = blockIdx.x * 256u + threadIdx.x;   // 524288 threads
    uint32_t nl = q & 63u;
    uint32_t wi = (q >> 6) & 31u;
    uint32_t c  = (q >> 11) & 3u;
    uint32_t nt = q >> 13;
    uint32_t n  = nt * 64u + nl;
    uint32_t kb = (c * 32u + wi) * 32u;
    uint32_t bits = 0;
    #pragma unroll
    for (int j = 0; j < 32; j++) {
        float v = w[(size_t)(kb + j) * NDIM + n];
        bits |= (v < 0.0f ? 1u : 0u) << j;
    }
    g_wbits[q] = bits;
}

__global__ void __launch_bounds__(256, 1) k_bgemm(float* __restrict__ out) {
    __shared__ uint32_t sm[2][2 * CHUNK_WORDS];
    const uint32_t sb = smem_u32(sm);

    const int tid  = threadIdx.x;
    const int warp = tid >> 5;
    const int lane = tid & 31;
    const int wm = warp >> 2;
    const int wn = warp & 3;
    const int mi = lane >> 2;
    const int ni = lane & 3;

    const uint32_t bid = blockIdx.x;
    const uint32_t ntb = bid & 63u;
    const uint32_t mtb = bid >> 6;                   // 0..83

    const uint32_t* aG = g_xbits + (size_t)mtb * (KW * 64);
    const uint32_t* bG = g_wbits + (size_t)ntb * (KW * 64);

    uint32_t ones[16], twos[16];
    int acc[16];
    #pragma unroll
    for (int o = 0; o < 16; o++) { ones[o] = 0; twos[o] = 0; acc[o] = 0; }

    auto load_chunk = [&](int buf, int c) {
        uint32_t base = sb + (uint32_t)(buf * 2 * CHUNK_WORDS * 4);
        const char* as = (const char*)(aG + (size_t)c * CHUNK_WORDS);
        const char* bs = (const char*)(bG + (size_t)c * CHUNK_WORDS);
        #pragma unroll
        for (int i = 0; i < 2; i++) {
            int q = tid + i * 256;
            cpasync16(base + (uint32_t)(q * 16), as + (size_t)q * 16);
            cpasync16(base + (uint32_t)(CHUNK_WORDS * 4) + (uint32_t)(q * 16),
                      bs + (size_t)q * 16);
        }
    };

    load_chunk(0, 0); CP_COMMIT();
    load_chunk(1, 1); CP_COMMIT();

    const int mrow = wm * 32 + mi * 4;
    const int ncol = wn * 16 + ni * 4;

    for (int c = 0; c < NCHUNK; c++) {
        CP_WAITN(1);
        __syncthreads();

        const uint32_t* A = sm[c & 1];
        const uint32_t* B = sm[c & 1] + CHUNK_WORDS;

        #pragma unroll
        for (int grp = 0; grp < CHUNK_W / 4; grp++) {
            uint32_t av[4][4], bv[4][4];
            #pragma unroll
            for (int w4 = 0; w4 < 4; w4++) {
                int w = grp * 4 + w4;
                #pragma unroll
                for (int mf = 0; mf < 4; mf++) av[mf][w4] = A[w * 64 + mrow + mf];
                #pragma unroll
                for (int nf = 0; nf < 4; nf++) bv[nf][w4] = B[w * 64 + ncol + nf];
            }
            #pragma unroll
            for (int mf = 0; mf < 4; mf++) {
                #pragma unroll
                for (int nf = 0; nf < 4; nf++) {
                    const int o = mf * 4 + nf;
                    uint32_t x0 = av[mf][0] ^ bv[nf][0];
                    uint32_t x1 = av[mf][1] ^ bv[nf][1];
                    uint32_t x2 = av[mf][2] ^ bv[nf][2];
                    uint32_t x3 = av[mf][3] ^ bv[nf][3];
                    uint32_t t0 = (ones[o] & x0) | (ones[o] & x1) | (x0 & x1);
                    ones[o] = ones[o] ^ x0 ^ x1;
                    uint32_t t1 = (ones[o] & x2) | (ones[o] & x3) | (x2 & x3);
                    ones[o] = ones[o] ^ x2 ^ x3;
                    uint32_t f = (twos[o] & t0) | (twos[o] & t1) | (t0 & t1);
                    twos[o] = twos[o] ^ t0 ^ t1;
                    acc[o] += __popc(f);
                }
            }
        }

        __syncthreads();
        if (c + 2 < NCHUNK) load_chunk(c & 1, c + 2);
        CP_COMMIT();
    }

    const uint32_t m0 = mtb * 64u + (uint32_t)mrow;
    const uint32_t n0 = ntb * 64u + (uint32_t)ncol;
    #pragma unroll
    for (int mf = 0; mf < 4; mf++) {
        float* orow = out + (size_t)(m0 + (uint32_t)mf) * NDIM + n0;
        #pragma unroll
        for (int nf = 0; nf < 4; nf++) {
            const int o = mf * 4 + nf;
            int D = (acc[o] << 2) + (__popc(twos[o]) << 1) + __popc(ones[o]);
            orow[nf] = (float)(KDIM - 2 * D);
        }
    }
}

// ===========================================================================
// S8 MMA PATH (rows 5376..8191) — verbatim R3 logic with row offset
// ===========================================================================
__global__ void __launch_bounds__(256) k_binx8(const float* __restrict__ x) {
    uint32_t q = blockIdx.x * 256u + threadIdx.x;   // 2816*1024 threads
    uint32_t ml = q >> 10;                           // local row 0..2815
    uint32_t w = q & 1023u;
    uint32_t m = 5376u + ml;
    float4 v = *reinterpret_cast<const float4*>(x + (size_t)m * KDIM + (size_t)w * 4u);
    uint32_t word = (uint32_t)sgn_s8(v.x) | ((uint32_t)sgn_s8(v.y) << 8)
                  | ((uint32_t)sgn_s8(v.z) << 16) | ((uint32_t)sgn_s8(v.w) << 24);
    uint32_t kt = w >> 4, wl = w & 15u;
    size_t tile = ((size_t)((ml >> 7) * (uint32_t)KT_S + kt)) * (size_t)A_TILE8;
    *reinterpret_cast<uint32_t*>(g_xa8 + tile + swoff8((int)(ml & 127u), (int)wl)) = word;
}

__global__ void __launch_bounds__(256) k_binw8(const float* __restrict__ w) {
    __shared__ unsigned char s[256][68];
    uint32_t bid = blockIdx.x;
    uint32_t nt = bid & 15u;
    uint32_t kt = bid >> 4;
    uint32_t n0 = nt * 256u, k0 = kt * 64u;

    #pragma unroll
    for (int it = 0; it < 16; it++) {
        uint32_t q = threadIdx.x + it * 256u;
        uint32_t kl = q >> 6;
        uint32_t nl = (q & 63u) << 2;
        float4 v = *reinterpret_cast<const float4*>(w + (size_t)(k0 + kl) * NDIM + n0 + nl);
        s[nl + 0][kl] = sgn_s8(v.x);
        s[nl + 1][kl] = sgn_s8(v.y);
        s[nl + 2][kl] = sgn_s8(v.z);
        s[nl + 3][kl] = sgn_s8(v.w);
    }
    __syncthreads();

    size_t tile = ((size_t)(nt * (uint32_t)KT_S + kt)) * (size_t)B_TILE8;
    #pragma unroll
    for (int it = 0; it < 16; it++) {
        uint32_t idx = threadIdx.x + it * 256u;
        uint32_t r = idx >> 4, wd = idx & 15u;
        uint32_t word = *reinterpret_cast<const uint32_t*>(&s[r][wd * 4]);
        *reinterpret_cast<uint32_t*>(g_wb8 + tile + swoff8((int)r, (int)wd)) = word;
    }
}

__global__ void __launch_bounds__(256, 1) k_gemm8(float* __restrict__ out) {
    extern __shared__ unsigned char smem[];
    const uint32_t sb = smem_u32(smem);
    const int tid  = threadIdx.x;
    const int warp = tid >> 5;
    const int lane = tid & 31;
    const int g    = lane >> 2;
    const int tig  = lane & 3;
    const int mbase = (warp >> 2) * 64;
    const int nbase = (warp & 3) * 64;

    const uint32_t bid = blockIdx.x;
    const uint32_t nt = bid & 15u;
    const uint32_t mtl = bid >> 4;                   // 0..21

    const unsigned char* aP = g_xa8 + (size_t)(mtl * (uint32_t)KT_S) * (size_t)A_TILE8;
    const unsigned char* bP = g_wb8 + (size_t)(nt  * (uint32_t)KT_S) * (size_t)B_TILE8;

    int acc[4][8][4];
    #pragma unroll
    for (int mf = 0; mf < 4; mf++)
        #pragma unroll
        for (int nf = 0; nf < 8; nf++)
            #pragma unroll
            for (int i = 0; i < 4; i++) acc[mf][nf][i] = 0;

    auto load_stage = [&](int s, int kt) {
        uint32_t base = sb + (uint32_t)(s * STAGE8);
        const unsigned char* as = aP + (size_t)kt * A_TILE8;
        const unsigned char* bs = bP + (size_t)kt * B_TILE8;
        #pragma unroll
        for (int i = 0; i < 2; i++) {
            int c = tid + i * 256;
            cpasync16(base + (uint32_t)(c * 16), as + (size_t)c * 16);
        }
        #pragma unroll
        for (int i = 0; i < 4; i++) {
            int c = tid + i * 256;
            cpasync16(base + (uint32_t)A_TILE8 + (uint32_t)(c * 16), bs + (size_t)c * 16);
        }
    };

    load_stage(0, 0); CP_COMMIT();
    load_stage(1, 1); CP_COMMIT();
    load_stage(2, 2); CP_COMMIT();

    for (int kt = 0; kt < KT_S; kt++) {
        CP_WAITN(2);
        __syncthreads();
        if (kt + 3 < KT_S) load_stage((kt + 3) & 3, kt + 3);
        CP_COMMIT();

        const uint32_t base  = sb + (uint32_t)((kt & 3) * STAGE8);
        const uint32_t baseB = base + (uint32_t)A_TILE8;

        #pragma unroll
        for (int kf = 0; kf < 2; kf++) {
            const int w0 = kf * 8 + tig;
            const int w1 = kf * 8 + 4 + tig;
            uint32_t a[4][4];
            #pragma unroll
            for (int mf = 0; mf < 4; mf++) {
                int r0 = mbase + mf * 16 + g;
                a[mf][0] = lds32(base + swoff8(r0,     w0));
                a[mf][1] = lds32(base + swoff8(r0 + 8, w0));
                a[mf][2] = lds32(base + swoff8(r0,     w1));
                a[mf][3] = lds32(base + swoff8(r0 + 8, w1));
            }
            uint32_t b[8][2];
            #pragma unroll
            for (int nf = 0; nf < 8; nf++) {
                int r = nbase + nf * 8 + g;
                b[nf][0] = lds32(baseB + swoff8(r, w0));
                b[nf][1] = lds32(baseB + swoff8(r, w1));
            }
            #pragma unroll
            for (int mf = 0; mf < 4; mf++)
                #pragma unroll
                for (int nf = 0; nf < 8; nf++)
                    mma_s8(acc[mf][nf], a[mf], b[nf]);
        }
        __syncthreads();
    }

    #pragma unroll
    for (int mf = 0; mf < 4; mf++) {
        int row = 5376 + (int)(mtl * 128u) + mbase + mf * 16 + g;
        float* o0 = out + (size_t)row * NDIM + nt * 256u + (uint32_t)(nbase + tig * 2);
        float* o1 = o0 + (size_t)8 * NDIM;
        #pragma unroll
        for (int nf = 0; nf < 8; nf++) {
            *reinterpret_cast<float2*>(o0 + nf * 8) =
                make_float2((float)acc[mf][nf][0], (float)acc[mf][nf][1]);
            *reinterpret_cast<float2*>(o1 + nf * 8) =
                make_float2((float)acc[mf][nf][2], (float)acc[mf][nf][3]);
        }
    }
}

// ---------------------------------------------------------------------------
// Launch: fork capture into two streams so the ALU-bound popc GEMM and the
// tensor-bound s8 mma GEMM run concurrently (parallel graph branches).
// ---------------------------------------------------------------------------
extern "C" void kernel_launch(void* const* d_in, const int* in_sizes, int n_in,
                              void* d_out, int out_size) {
    const float* x = (const float*)d_in[0];
    const float* w = (const float*)d_in[1];
    float* out = (float*)d_out;
    (void)in_sizes; (void)n_in; (void)out_size;

    cudaFuncSetAttribute(k_gemm8, cudaFuncAttributeMaxDynamicSharedMemorySize, SMEM8);

    cudaStream_t s2;
    cudaStreamCreateWithFlags(&s2, cudaStreamNonBlocking);
    cudaEvent_t eFork, eJoin;
    cudaEventCreateWithFlags(&eFork, cudaEventDisableTiming);
    cudaEventCreateWithFlags(&eJoin, cudaEventDisableTiming);

    // Fork: s2 branches off the (possibly capturing) main stream.
    cudaEventRecord(eFork, 0);
    cudaStreamWaitEvent(s2, eFork, 0);

    // --- branch B (s2): s8 mma path, rows 5376..8191 ---
    k_binx8<<<(2816 * 1024) / 256, 256, 0, s2>>>(x);   // 11264 blocks
    k_binw8<<<NT_S * KT_S, 256, 0, s2>>>(w);           // 1024 blocks
    k_gemm8<<<MT_S * NT_S, 256, SMEM8, s2>>>(out);     // 352 blocks

    // --- branch A (main): popc path, rows 0..5375 ---
    k_packx<<<5376 / 8, 256>>>(x);                     // 672 blocks
    k_packw<<<(NT_P * KW * 64) / 256, 256>>>(w);       // 2048 blocks
    k_bgemm<<<MT_P * NT_P, 256>>>(out);                // 5376 blocks

    // Join: main stream waits for branch B.
    cudaEventRecord(eJoin, s2);
    cudaStreamWaitEvent(0, eJoin, 0);
    // NOTE: stream/events intentionally not destroyed here — destroying a
    // stream participating in an ongoing capture would invalidate the graph.
}

// round 8
// speedup vs baseline: 1.3977x; 1.3977x over previous
#include <cuda_runtime.h>
#include <cstdint>

// ============================================================================
// out[8192,4096] = sign(x[8192,4096]) @ sign(w[4096,4096])
//
// Pure XOR+CSA popcount GEMM (ALU pipe), exact integer arithmetic:
//   dot = 4096 - 2*popc(xbits ^ wbits)
// R7 refinements over the 1047us R5 kernel:
//   - whole-K resident in smem (64KB/block), 2 waits + 2 syncs total
//   - ld.shared.v4 fragment loads (4x fewer LDS issue slots, swizzle-free)
//   - float4 epilogue stores
//   - __launch_bounds__(256,2) -> 2 blocks/SM co-resident
// ============================================================================

static constexpr int MDIM = 8192;
static constexpr int NDIM = 4096;
static constexpr int KDIM = 4096;
static constexpr int KW   = KDIM / 32;   // 128 words per row

static constexpr int MT = MDIM / 64;     // 128 tiles (64 rows)
static constexpr int NT = NDIM / 64;     // 64 tiles (64 cols)

// Packed bit scratch, word-major per tile:
//   g_xbits[mt][w][m]  (mt<128, w<128, m<64)
//   g_wbits[nt][w][n]  (nt<64,  w<128, n<64)
__device__ __align__(16) uint32_t g_xbits[(size_t)MT * KW * 64];   // 4 MB
__device__ __align__(16) uint32_t g_wbits[(size_t)NT * KW * 64];   // 2 MB

// ---------------------------------------------------------------------------
__device__ __forceinline__ uint32_t smem_u32(const void* p) {
    uint32_t a;
    asm("{ .reg .u64 t; cvta.to.shared.u64 t, %1; cvt.u32.u64 %0, t; }" : "=r"(a) : "l"(p));
    return a;
}
__device__ __forceinline__ void cpasync16(uint32_t s, const void* g) {
    asm volatile("cp.async.cg.shared.global [%0], [%1], 16;" :: "r"(s), "l"(g));
}
#define CP_COMMIT() asm volatile("cp.async.commit_group;" ::: "memory")
#define CP_WAITN(n) asm volatile("cp.async.wait_group %0;" :: "n"(n) : "memory")

// ---------------------------------------------------------------------------
// Pack x: one warp per row; ballot packs 32 signs per word.
// ---------------------------------------------------------------------------
__global__ void __launch_bounds__(256) k_packx(const float* __restrict__ x) {
    int m    = blockIdx.x * 8 + (threadIdx.x >> 5);    // 0..8191
    int lane = threadIdx.x & 31;
    const float* row = x + (size_t)m * KDIM;
    uint32_t mt = (uint32_t)m >> 6, ml = (uint32_t)m & 63u;
    uint32_t* dst = g_xbits + (size_t)mt * (KW * 64) + ml;
    #pragma unroll 4
    for (int w = 0; w < KW; w++) {
        float v = row[w * 32 + lane];
        uint32_t bits = __ballot_sync(0xffffffffu, v < 0.0f);
        if (lane == 0) dst[(size_t)w * 64] = bits;
    }
}

// ---------------------------------------------------------------------------
// Pack w transposed: thread q builds word (column n, 32 consecutive k);
// output index == q (fully coalesced stores).
// ---------------------------------------------------------------------------
__global__ void __launch_bounds__(256) k_packw(const float* __restrict__ w) {
    uint32_t q  = blockIdx.x * 256u + threadIdx.x;   // 524288 threads
    uint32_t nl = q & 63u;
    uint32_t W  = (q >> 6) & 127u;
    uint32_t nt = q >> 13;
    uint32_t n  = nt * 64u + nl;
    uint32_t kb = W * 32u;
    uint32_t bits = 0;
    #pragma unroll
    for (int j = 0; j < 32; j++) {
        float v = w[(size_t)(kb + j) * NDIM + n];
        bits |= (v < 0.0f ? 1u : 0u) << j;
    }
    g_wbits[q] = bits;
}

// ---------------------------------------------------------------------------
// Binary GEMM: 64x64 tile, 256 threads, 16 outputs/thread (4m x 4n).
// Whole K (128 words) resident in smem; halves arrive via 2 cp.async groups.
// ---------------------------------------------------------------------------
__global__ void __launch_bounds__(256, 2) k_bgemm(float* __restrict__ out) {
    extern __shared__ uint32_t sm[];                 // [A: 128*64 | B: 128*64]
    uint32_t* smA = sm;
    uint32_t* smB = sm + KW * 64;
    const uint32_t sbA = smem_u32(smA);
    const uint32_t sbB = smem_u32(smB);

    const int tid  = threadIdx.x;
    const int warp = tid >> 5;
    const int lane = tid & 31;
    const int wm = warp >> 2;        // 0..1
    const int wn = warp & 3;         // 0..3
    const int mi = lane >> 2;        // 0..7
    const int ni = lane & 3;         // 0..3
    const int mrow = wm * 32 + mi * 4;   // first of 4 consecutive m rows
    const int ncol = wn * 16 + ni * 4;   // first of 4 consecutive n cols

    const uint32_t bid = blockIdx.x;
    const uint32_t ntb = bid & 63u;
    const uint32_t mtb = bid >> 6;

    const char* aG = (const char*)(g_xbits + (size_t)mtb * (KW * 64));
    const char* bG = (const char*)(g_wbits + (size_t)ntb * (KW * 64));

    // Issue both halves: half h = words [h*64, h*64+64), 16KB per matrix.
    #pragma unroll
    for (int h = 0; h < 2; h++) {
        #pragma unroll
        for (int i = 0; i < 4; i++) {
            int c = tid + i * 256;                   // 0..1023 16B-chunks
            cpasync16(sbA + (uint32_t)(h * 16384 + c * 16), aG + (size_t)h * 16384 + (size_t)c * 16);
            cpasync16(sbB + (uint32_t)(h * 16384 + c * 16), bG + (size_t)h * 16384 + (size_t)c * 16);
        }
        CP_COMMIT();
    }

    uint32_t ones[16], twos[16];
    int acc[16];
    #pragma unroll
    for (int o = 0; o < 16; o++) { ones[o] = 0; twos[o] = 0; acc[o] = 0; }

    CP_WAITN(1);
    __syncthreads();

    #pragma unroll 2
    for (int half = 0; half < 2; half++) {
        if (half == 1) { CP_WAITN(0); __syncthreads(); }

        #pragma unroll
        for (int grp = 0; grp < 16; grp++) {
            const int gw = half * 64 + grp * 4;      // first word of group
            uint32_t av[4][4], bv[4][4];
            #pragma unroll
            for (int w4 = 0; w4 < 4; w4++) {
                uint4 A = *reinterpret_cast<const uint4*>(smA + (gw + w4) * 64 + mrow);
                uint4 B = *reinterpret_cast<const uint4*>(smB + (gw + w4) * 64 + ncol);
                av[0][w4] = A.x; av[1][w4] = A.y; av[2][w4] = A.z; av[3][w4] = A.w;
                bv[0][w4] = B.x; bv[1][w4] = B.y; bv[2][w4] = B.z; bv[3][w4] = B.w;
            }
            #pragma unroll
            for (int mf = 0; mf < 4; mf++) {
                #pragma unroll
                for (int nf = 0; nf < 4; nf++) {
                    const int o = mf * 4 + nf;
                    uint32_t x0 = av[mf][0] ^ bv[nf][0];
                    uint32_t x1 = av[mf][1] ^ bv[nf][1];
                    uint32_t x2 = av[mf][2] ^ bv[nf][2];
                    uint32_t x3 = av[mf][3] ^ bv[nf][3];
                    // CSA(ones, x0, x1) -> t0
                    uint32_t t0 = (ones[o] & x0) | (ones[o] & x1) | (x0 & x1);
                    ones[o] = ones[o] ^ x0 ^ x1;
                    // CSA(ones, x2, x3) -> t1
                    uint32_t t1 = (ones[o] & x2) | (ones[o] & x3) | (x2 & x3);
                    ones[o] = ones[o] ^ x2 ^ x3;
                    // CSA(twos, t0, t1) -> f (weight 4)
                    uint32_t f = (twos[o] & t0) | (twos[o] & t1) | (t0 & t1);
                    twos[o] = twos[o] ^ t0 ^ t1;
                    acc[o] += __popc(f);
                }
            }
        }
    }

    // Epilogue: D = 4*acc + 2*popc(twos) + popc(ones); dot = 4096 - 2D.
    const uint32_t m0 = mtb * 64u + (uint32_t)mrow;
    const uint32_t n0 = ntb * 64u + (uint32_t)ncol;
    #pragma unroll
    for (int mf = 0; mf < 4; mf++) {
        float4 v;
        {
            const int o = mf * 4;
            int D0 = (acc[o+0] << 2) + (__popc(twos[o+0]) << 1) + __popc(ones[o+0]);
            int D1 = (acc[o+1] << 2) + (__popc(twos[o+1]) << 1) + __popc(ones[o+1]);
            int D2 = (acc[o+2] << 2) + (__popc(twos[o+2]) << 1) + __popc(ones[o+2]);
            int D3 = (acc[o+3] << 2) + (__popc(twos[o+3]) << 1) + __popc(ones[o+3]);
            v = make_float4((float)(KDIM - 2 * D0), (float)(KDIM - 2 * D1),
                            (float)(KDIM - 2 * D2), (float)(KDIM - 2 * D3));
        }
        *reinterpret_cast<float4*>(out + (size_t)(m0 + (uint32_t)mf) * NDIM + n0) = v;
    }
}

// ---------------------------------------------------------------------------
// Launch
// ---------------------------------------------------------------------------
extern "C" void kernel_launch(void* const* d_in, const int* in_sizes, int n_in,
                              void* d_out, int out_size) {
    const float* x = (const float*)d_in[0];   // [8192, 4096]
    const float* w = (const float*)d_in[1];   // [4096, 4096] (k-major)
    float* out = (float*)d_out;               // [8192, 4096]
    (void)in_sizes; (void)n_in; (void)out_size;

    static constexpr int SMEM = 2 * KW * 64 * 4;   // 65536 B
    cudaFuncSetAttribute(k_bgemm, cudaFuncAttributeMaxDynamicSharedMemorySize, SMEM);

    k_packx<<<MDIM / 8, 256>>>(x);                 // 1024 blocks
    k_packw<<<(NT * KW * 64) / 256, 256>>>(w);     // 2048 blocks
    k_bgemm<<<MT * NT, 256, SMEM>>>(out);          // 8192 blocks
}